// round 15
// baseline (speedup 1.0000x reference)
#include <cuda_runtime.h>
#include <cuda_bf16.h>
#include <cstdint>

#define T_LEN   16384
#define B_SZ    16
#define TS_OUT  96
#define NBLK    171
#define SLOPE_F 0.22916666666666666f
#define MUS_N   (B_SZ * (T_LEN - 32))

#define ACT_STRB 144
#define ACTH_B   0
#define ACTL_B   20736
#define BST0_B   41472
#define BST1_B   74240
#define XS_B     107008
#define HS_B     107536
#define CBS_B    110608
#define MW0_B    111408
#define MW1_B    112432
#define MW2_B    113456
#define MB0_B    113520
#define MB1_B    113584
#define MB2_B    113648
#define SMEM_TOTAL 113664

// fragment-major weight images: [l][tap][nt][kt][lane]{bh0,bh1,bl0,bl1}
__device__ __align__(16) uint32_t g_wf[24576];
// layer4: [tap][kt][lane]{bh0,bh1,bl0,bl1}
__device__ __align__(16) uint32_t g_wf4[1024];
__device__ float g_mus[B_SZ * T_LEN];

__device__ __forceinline__ float rrelu(float v) { return v >= 0.f ? v : v * SLOPE_F; }

__device__ __forceinline__ uint32_t smem_u32(const void* p) {
    uint32_t a;
    asm("{ .reg .u64 t; cvta.to.shared.u64 t, %1; cvt.u32.u64 %0, t; }" : "=r"(a) : "l"(p));
    return a;
}
__device__ __forceinline__ uint32_t bfpack(__nv_bfloat16 lo, __nv_bfloat16 hi) {
    return ((uint32_t)__bfloat16_as_ushort(hi) << 16) | __bfloat16_as_ushort(lo);
}
__device__ __forceinline__ void split_pack(float v0, float v1, uint32_t& hi, uint32_t& lo) {
    __nv_bfloat16 h0 = __float2bfloat16(v0);
    __nv_bfloat16 h1 = __float2bfloat16(v1);
    __nv_bfloat16 l0 = __float2bfloat16(v0 - __bfloat162float(h0));
    __nv_bfloat16 l1 = __float2bfloat16(v1 - __bfloat162float(h1));
    hi = bfpack(h0, h1);
    lo = bfpack(l0, l1);
}
__device__ __forceinline__ void ldmx4(uint32_t* r, uint32_t addr) {
    asm volatile("ldmatrix.sync.aligned.m8n8.x4.shared.b16 {%0,%1,%2,%3}, [%4];"
                 : "=r"(r[0]), "=r"(r[1]), "=r"(r[2]), "=r"(r[3]) : "r"(addr));
}
__device__ __forceinline__ void mma16816(float* d, const uint32_t* a, uint32_t b0, uint32_t b1) {
    asm volatile(
        "mma.sync.aligned.m16n8k16.row.col.f32.bf16.bf16.f32 "
        "{%0,%1,%2,%3}, {%4,%5,%6,%7}, {%8,%9}, {%0,%1,%2,%3};"
        : "+f"(d[0]), "+f"(d[1]), "+f"(d[2]), "+f"(d[3])
        : "r"(a[0]), "r"(a[1]), "r"(a[2]), "r"(a[3]), "r"(b0), "r"(b1));
}

// -------- build fragment-major bf16-split weight images --------
__global__ void reorder_kernel(const float* __restrict__ cw1, const float* __restrict__ cw2,
                               const float* __restrict__ cw3, const float* __restrict__ cw4) {
    int idx = blockIdx.x * blockDim.x + threadIdx.x;
    if (idx < 24576) {
        int u = idx & 3, lane = (idx >> 2) & 31, kt = (idx >> 7) & 3;
        int nt = (idx >> 9) & 7, tap = (idx >> 12) & 1, l = idx >> 13;
        int split = u >> 1, reg = u & 1;
        const float* src = (l == 0) ? cw1 : (l == 1) ? cw2 : cw3;
        int n  = nt * 8 + (lane >> 2);
        int k0 = kt * 16 + (lane & 3) * 2 + reg * 8;
        float wa = src[(n * 64 + k0) * 2 + tap];
        float wb = src[(n * 64 + k0 + 1) * 2 + tap];
        __nv_bfloat16 ha = __float2bfloat16(wa), hb = __float2bfloat16(wb);
        __nv_bfloat16 va = split ? __float2bfloat16(wa - __bfloat162float(ha)) : ha;
        __nv_bfloat16 vb = split ? __float2bfloat16(wb - __bfloat162float(hb)) : hb;
        g_wf[idx] = bfpack(va, vb);
    } else if (idx < 24576 + 1024) {
        int r2 = idx - 24576;
        int u = r2 & 3, lane = (r2 >> 2) & 31, kt = (r2 >> 7) & 3, tap = (r2 >> 9) & 1;
        int split = u >> 1, reg = u & 1;
        int n  = lane >> 2;
        int k0 = kt * 16 + (lane & 3) * 2 + reg * 8;
        float wa = cw4[(n * 64 + k0) * 2 + tap];
        float wb = cw4[(n * 64 + k0 + 1) * 2 + tap];
        __nv_bfloat16 ha = __float2bfloat16(wa), hb = __float2bfloat16(wb);
        __nv_bfloat16 va = split ? __float2bfloat16(wa - __bfloat162float(ha)) : ha;
        __nv_bfloat16 vb = split ? __float2bfloat16(wb - __bfloat162float(hb)) : hb;
        g_wf4[r2] = bfpack(va, vb);
    }
}

// -------- fused conv stack: HMMA, double-buffered smem B, occ 2 --------
__global__ __launch_bounds__(256, 2)
void conv_mma_kernel(const float* __restrict__ x,
                     const float* __restrict__ cw0, const float* __restrict__ cb0,
                     const float* __restrict__ cb1, const float* __restrict__ cb2,
                     const float* __restrict__ cb3, const float* __restrict__ cb4,
                     const float* __restrict__ mw0, const float* __restrict__ mb0,
                     const float* __restrict__ mw1, const float* __restrict__ mb1,
                     const float* __restrict__ mw2, const float* __restrict__ mb2,
                     const float* __restrict__ gumbel,
                     float* __restrict__ out_z) {
    extern __shared__ char smem[];
    const uint32_t sb = smem_u32(smem);
    const int tid = threadIdx.x, wp = tid >> 5, lane = tid & 31;
    const int b = blockIdx.y;
    const int t0 = blockIdx.x * TS_OUT;
    const int mrow = wp * 16;

    float* xs   = (float*)(smem + XS_B);
    float* hs   = (float*)(smem + HS_B);
    float* cbs  = (float*)(smem + CBS_B);
    float* mw0s = (float*)(smem + MW0_B);
    float* mw1s = (float*)(smem + MW1_B);
    float* mw2s = (float*)(smem + MW2_B);
    float* mb0s = (float*)(smem + MB0_B);
    float* mb1s = (float*)(smem + MB1_B);
    float* mb2s = (float*)(smem + MB2_B);

    for (int j = tid; j < 132; j += 256) {
        int g = t0 + j - 31;
        xs[j] = (g >= 0 && g < T_LEN) ? __ldg(x + (size_t)b * T_LEN + g) : 0.f;
    }
    for (int i = tid; i < 200; i += 256)
        cbs[i] = (i < 64) ? __ldg(cb1 + i) : (i < 128) ? __ldg(cb2 + i - 64)
               : (i < 192) ? __ldg(cb3 + i - 128) : __ldg(cb4 + i - 192);
    mw0s[tid] = __ldg(mw0 + tid);
    mw1s[tid] = __ldg(mw1 + tid);
    if (tid < 16) { mw2s[tid] = mw2[tid]; mb0s[tid] = mb0[tid]; mb1s[tid] = mb1[tid]; }
    if (tid == 0) mb2s[0] = mb2[0];
    // zero halo rows 128..143
    for (int i = tid; i < 576; i += 256) {
        int r = 128 + i / 36, w = i % 36;
        *(uint32_t*)(smem + ACTH_B + r * ACT_STRB + w * 4) = 0;
        *(uint32_t*)(smem + ACTL_B + r * ACT_STRB + w * 4) = 0;
    }
    // stage layer-0 B image into BST0
    {
        const uint4* src = (const uint4*)g_wf;
        uint4* dst = (uint4*)(smem + BST0_B);
#pragma unroll
        for (int i = 0; i < 8; i++) dst[tid + i * 256] = __ldg(src + tid + i * 256);
    }
    __syncthreads();  // xs / weights / halo / BST0 visible to ALL warps (R14 bug: this was missing)

    // ---- layer 0: 1 -> 64, d=1 (scalar, all 256 threads: 2 per row) ----
    {
        const int row = tid & 127, half = tid >> 7;
        float xa = xs[row], xb = xs[row + 1];
        char* ph = smem + ACTH_B + row * ACT_STRB + half * 64;
        char* pl = smem + ACTL_B + row * ACT_STRB + half * 64;
        const int cb_ = half * 32;
#pragma unroll 4
        for (int cc = 0; cc < 32; cc += 2) {
            int c = cb_ + cc;
            float v0 = rrelu(__ldg(cb0 + c)     + __ldg(cw0 + 2 * c)     * xa + __ldg(cw0 + 2 * c + 1) * xb);
            float v1 = rrelu(__ldg(cb0 + c + 1) + __ldg(cw0 + 2 * c + 2) * xa + __ldg(cw0 + 2 * c + 3) * xb);
            uint32_t hi, lo;
            split_pack(v0, v1, hi, lo);
            *(uint32_t*)(ph + 2 * cc) = hi;
            *(uint32_t*)(pl + 2 * cc) = lo;
        }
    }
    __syncthreads();

    // ---- mid layers via mma.sync, B in smem, prefetch next layer ----
    const int dil[3] = {2, 4, 8};
#pragma unroll
    for (int l = 0; l < 3; l++) {
        const int D = dil[l];
        const int bcur = (l & 1) ? BST1_B : BST0_B;
        const int bnxt = (l & 1) ? BST0_B : BST1_B;

        uint4 pf[8];
        if (l < 2) {
            const uint4* src = (const uint4*)(g_wf + (l + 1) * 8192);
#pragma unroll
            for (int i = 0; i < 8; i++) pf[i] = __ldg(src + tid + i * 256);
        }

        float acc[8][4];
#pragma unroll
        for (int nt = 0; nt < 8; nt++)
#pragma unroll
            for (int q = 0; q < 4; q++) acc[nt][q] = 0.f;

#pragma unroll
        for (int tap = 0; tap < 2; tap++) {
            uint32_t abase = sb + (uint32_t)(mrow + tap * D + (lane & 15)) * ACT_STRB + (lane & 16);
#pragma unroll
            for (int kt = 0; kt < 4; kt++) {
                uint32_t ah[4], al[4];
                ldmx4(ah, abase + ACTH_B + kt * 32);
                ldmx4(al, abase + ACTL_B + kt * 32);
#pragma unroll
                for (int nt = 0; nt < 8; nt++) {
                    uint4 bv = *(const uint4*)(smem + bcur +
                               ((((tap * 8 + nt) * 4 + kt) << 5) + lane) * 16);
                    mma16816(acc[nt], ah, bv.x, bv.y);
                    mma16816(acc[nt], al, bv.x, bv.y);
                    mma16816(acc[nt], ah, bv.z, bv.w);
                }
            }
        }
        __syncthreads();  // all reads of act + bcur done
        if (l < 2) {
            uint4* dst = (uint4*)(smem + bnxt);
#pragma unroll
            for (int i = 0; i < 8; i++) dst[tid + i * 256] = pf[i];
        }
        // epilogue: bias + rrelu + split, overwrite act rows 0..127
        const float* bias = cbs + 64 * l;
        const int r1 = mrow + (lane >> 2);
#pragma unroll
        for (int nt = 0; nt < 8; nt++) {
            int c0 = nt * 8 + (lane & 3) * 2;
            uint32_t hi, lo;
            split_pack(rrelu(acc[nt][0] + bias[c0]), rrelu(acc[nt][1] + bias[c0 + 1]), hi, lo);
            *(uint32_t*)(smem + ACTH_B + r1 * ACT_STRB + c0 * 2) = hi;
            *(uint32_t*)(smem + ACTL_B + r1 * ACT_STRB + c0 * 2) = lo;
            split_pack(rrelu(acc[nt][2] + bias[c0]), rrelu(acc[nt][3] + bias[c0 + 1]), hi, lo);
            *(uint32_t*)(smem + ACTH_B + (r1 + 8) * ACT_STRB + c0 * 2) = hi;
            *(uint32_t*)(smem + ACTL_B + (r1 + 8) * ACT_STRB + c0 * 2) = lo;
        }
        __syncthreads();
    }

    // ---- layer 4: 64 -> 8, d=16, N=8 (warps 0..5, rows 0..95) ----
    if (wp < 6) {
        float a4[4] = {0.f, 0.f, 0.f, 0.f};
#pragma unroll
        for (int tap = 0; tap < 2; tap++) {
            uint32_t abase = sb + (uint32_t)(mrow + tap * 16 + (lane & 15)) * ACT_STRB + (lane & 16);
#pragma unroll
            for (int kt = 0; kt < 4; kt++) {
                uint32_t ah[4], al[4];
                ldmx4(ah, abase + ACTH_B + kt * 32);
                ldmx4(al, abase + ACTL_B + kt * 32);
                uint4 bv = __ldg(((const uint4*)g_wf4) + (((tap * 4 + kt) << 5) + lane));
                mma16816(a4, ah, bv.x, bv.y);
                mma16816(a4, al, bv.x, bv.y);
                mma16816(a4, ah, bv.z, bv.w);
            }
        }
        const int r1 = mrow + (lane >> 2), c0 = (lane & 3) * 2;
        hs[r1 * 8 + c0]           = rrelu(a4[0] + cbs[192 + c0]);
        hs[r1 * 8 + c0 + 1]       = rrelu(a4[1] + cbs[192 + c0 + 1]);
        hs[(r1 + 8) * 8 + c0]     = rrelu(a4[2] + cbs[192 + c0]);
        hs[(r1 + 8) * 8 + c0 + 1] = rrelu(a4[3] + cbs[192 + c0 + 1]);
    }
    __syncthreads();

    // ---- gumbel softmax + MLP + mus ----
    {
        const int j = tid, t = t0 + j;
        if (j < TS_OUT && t < T_LEN) {
            float l8[8], gmb[8];
#pragma unroll
            for (int r = 0; r < 8; r++) l8[r] = hs[j * 8 + r];
            const float4* gp = (const float4*)(gumbel + ((size_t)b * T_LEN + t) * 8);
            float4 g0 = __ldg(gp), g1 = __ldg(gp + 1);
            gmb[0] = g0.x; gmb[1] = g0.y; gmb[2] = g0.z; gmb[3] = g0.w;
            gmb[4] = g1.x; gmb[5] = g1.y; gmb[6] = g1.z; gmb[7] = g1.w;
            float a[8], mx = -1e30f;
#pragma unroll
            for (int r = 0; r < 8; r++) { a[r] = (l8[r] + gmb[r]) * 10.f; mx = fmaxf(mx, a[r]); }
            float e[8], s = 0.f;
#pragma unroll
            for (int r = 0; r < 8; r++) { e[r] = __expf(a[r] - mx); s += e[r]; }
            float inv = 1.f / s;
            float z[8];
#pragma unroll
            for (int r = 0; r < 8; r++) {
                z[r] = e[r] * inv;
                out_z[((size_t)b * 8 + r) * T_LEN + t] = z[r];
            }
            float v[16];
#pragma unroll
            for (int r = 0; r < 8; r++) { v[r] = z[r]; v[8 + r] = l8[r]; }
            float m1[16];
#pragma unroll
            for (int o = 0; o < 16; o++) {
                float s2 = mb0s[o];
#pragma unroll
                for (int ci = 0; ci < 16; ci++) s2 += mw0s[o * 16 + ci] * v[ci];
                m1[o] = rrelu(s2);
            }
            float m2[16];
#pragma unroll
            for (int o = 0; o < 16; o++) {
                float s2 = mb1s[o];
#pragma unroll
                for (int ci = 0; ci < 16; ci++) s2 += mw1s[o * 16 + ci] * m1[ci];
                m2[o] = rrelu(s2);
            }
            float mu = mb2s[0];
#pragma unroll
            for (int ci = 0; ci < 16; ci++) mu += mw2s[ci] * m2[ci];
            g_mus[(size_t)b * T_LEN + t] = mu;
        }
    }
}

// -------- epilogue: windowed Fisher correction (proven) --------
__global__ __launch_bounds__(256)
void final_kernel(const float* __restrict__ x,
                  const float* __restrict__ sqrt_cov,
                  const float* __restrict__ fish,
                  const float* __restrict__ z_all,
                  float* __restrict__ out_mus) {
    __shared__ float xsm[288], msm[288], fsh[256], scs[8];
    const int tid = threadIdx.x;
    const int b   = blockIdx.y;
    const int p0  = blockIdx.x * 256;

    for (int i = tid; i < 288; i += 256) {
        int g = p0 + i;
        bool ok = g < T_LEN;
        xsm[i] = ok ? __ldg(x + (size_t)b * T_LEN + g) : 0.f;
        msm[i] = ok ? g_mus[(size_t)b * T_LEN + g] : 0.f;
    }
    if (tid < 256) fsh[tid] = __ldg(fish + tid);
    if (tid < 8)   scs[tid] = __ldg(sqrt_cov + tid);
    __syncthreads();

    const int p = p0 + tid;
    if (p < T_LEN - 32) {
        const int tau = p + 32;
        float z[8], cov = 0.f;
#pragma unroll
        for (int r = 0; r < 8; r++) {
            z[r] = __ldg(z_all + ((size_t)b * 8 + r) * T_LEN + tau);
            cov += z[r] * scs[r];
        }
        cov *= cov;
        float fj[32];
#pragma unroll
        for (int w = 0; w < 32; w++) fj[w] = 0.f;
#pragma unroll
        for (int r = 0; r < 8; r++)
#pragma unroll
            for (int w = 0; w < 32; w++)
                fj[w] += z[r] * fsh[r * 32 + w];
        float s = 0.f;
#pragma unroll
        for (int w = 0; w < 32; w++)
            s += fj[w] * (xsm[tid + w] - msm[tid + w]);
        out_mus[(size_t)b * (T_LEN - 32) + p] = msm[tid + 32] - cov * s;
    }
}

extern "C" void kernel_launch(void* const* d_in, const int* in_sizes, int n_in,
                              void* d_out, int out_size) {
    const float* x    = (const float*)d_in[0];
    const float* cw0  = (const float*)d_in[1];
    const float* cb0  = (const float*)d_in[2];
    const float* cw1  = (const float*)d_in[3];
    const float* cb1  = (const float*)d_in[4];
    const float* cw2  = (const float*)d_in[5];
    const float* cb2  = (const float*)d_in[6];
    const float* cw3  = (const float*)d_in[7];
    const float* cb3  = (const float*)d_in[8];
    const float* cw4  = (const float*)d_in[9];
    const float* cb4  = (const float*)d_in[10];
    const float* mw0  = (const float*)d_in[11];
    const float* mb0  = (const float*)d_in[12];
    const float* mw1  = (const float*)d_in[13];
    const float* mb1  = (const float*)d_in[14];
    const float* mw2  = (const float*)d_in[15];
    const float* mb2  = (const float*)d_in[16];
    const float* scv  = (const float*)d_in[17];
    const float* fish = (const float*)d_in[18];
    const float* gmb  = (const float*)d_in[19];

    float* out     = (float*)d_out;
    float* out_mus = out;
    float* out_z   = out + MUS_N;

    cudaFuncSetAttribute(conv_mma_kernel, cudaFuncAttributeMaxDynamicSharedMemorySize, SMEM_TOTAL);

    reorder_kernel<<<100, 256>>>(cw1, cw2, cw3, cw4);
    conv_mma_kernel<<<dim3(NBLK, B_SZ), 256, SMEM_TOTAL>>>(
        x, cw0, cb0, cb1, cb2, cb3, cb4, mw0, mb0, mw1, mb1, mw2, mb2, gmb, out_z);
    final_kernel<<<dim3((T_LEN - 32 + 255) / 256, B_SZ), 256>>>(x, scv, fish, out_z, out_mus);
}

// round 17
// speedup vs baseline: 1.7978x; 1.7978x over previous
#include <cuda_runtime.h>
#include <cuda_bf16.h>
#include <cstdint>

#define T_LEN   16384
#define B_SZ    16
#define TS_OUT  96
#define NBLK    171
#define SLOPE_F 0.22916666666666666f
#define MUS_N   (B_SZ * (T_LEN - 32))

#define ACT_STRB 144
#define ACTH_B   0
#define ACTL_B   20736
#define XS_B     41472
#define HS_B     42000
#define CBS_B    45072
#define MW0_B    45872
#define MW1_B    46896
#define MW2_B    47920
#define MB0_B    47984
#define MB1_B    48048
#define MB2_B    48112
#define SMEM_TOTAL 48128

// fragment-major weight images: [l][tap][nt][kt][lane]{bh0,bh1,bl0,bl1}
__device__ __align__(16) uint32_t g_wf[24576];
// layer4: [tap][kt][lane]{bh0,bh1,bl0,bl1}
__device__ __align__(16) uint32_t g_wf4[1024];
__device__ float g_mus[B_SZ * T_LEN];

__device__ __forceinline__ float rrelu(float v) { return v >= 0.f ? v : v * SLOPE_F; }

__device__ __forceinline__ uint32_t smem_u32(const void* p) {
    uint32_t a;
    asm("{ .reg .u64 t; cvta.to.shared.u64 t, %1; cvt.u32.u64 %0, t; }" : "=r"(a) : "l"(p));
    return a;
}
__device__ __forceinline__ uint32_t bfpack(__nv_bfloat16 lo, __nv_bfloat16 hi) {
    return ((uint32_t)__bfloat16_as_ushort(hi) << 16) | __bfloat16_as_ushort(lo);
}
__device__ __forceinline__ void split_pack(float v0, float v1, uint32_t& hi, uint32_t& lo) {
    __nv_bfloat16 h0 = __float2bfloat16(v0);
    __nv_bfloat16 h1 = __float2bfloat16(v1);
    __nv_bfloat16 l0 = __float2bfloat16(v0 - __bfloat162float(h0));
    __nv_bfloat16 l1 = __float2bfloat16(v1 - __bfloat162float(h1));
    hi = bfpack(h0, h1);
    lo = bfpack(l0, l1);
}
__device__ __forceinline__ void ldmx4(uint32_t* r, uint32_t addr) {
    asm volatile("ldmatrix.sync.aligned.m8n8.x4.shared.b16 {%0,%1,%2,%3}, [%4];"
                 : "=r"(r[0]), "=r"(r[1]), "=r"(r[2]), "=r"(r[3]) : "r"(addr));
}
__device__ __forceinline__ void mma16816(float* d, const uint32_t* a, uint32_t b0, uint32_t b1) {
    asm volatile(
        "mma.sync.aligned.m16n8k16.row.col.f32.bf16.bf16.f32 "
        "{%0,%1,%2,%3}, {%4,%5,%6,%7}, {%8,%9}, {%0,%1,%2,%3};"
        : "+f"(d[0]), "+f"(d[1]), "+f"(d[2]), "+f"(d[3])
        : "r"(a[0]), "r"(a[1]), "r"(a[2]), "r"(a[3]), "r"(b0), "r"(b1));
}

// -------- build fragment-major bf16-split weight images --------
__global__ void reorder_kernel(const float* __restrict__ cw1, const float* __restrict__ cw2,
                               const float* __restrict__ cw3, const float* __restrict__ cw4) {
    int idx = blockIdx.x * blockDim.x + threadIdx.x;
    if (idx < 24576) {
        int u = idx & 3, lane = (idx >> 2) & 31, kt = (idx >> 7) & 3;
        int nt = (idx >> 9) & 7, tap = (idx >> 12) & 1, l = idx >> 13;
        int split = u >> 1, reg = u & 1;
        const float* src = (l == 0) ? cw1 : (l == 1) ? cw2 : cw3;
        int n  = nt * 8 + (lane >> 2);
        int k0 = kt * 16 + (lane & 3) * 2 + reg * 8;
        float wa = src[(n * 64 + k0) * 2 + tap];
        float wb = src[(n * 64 + k0 + 1) * 2 + tap];
        __nv_bfloat16 ha = __float2bfloat16(wa), hb = __float2bfloat16(wb);
        __nv_bfloat16 va = split ? __float2bfloat16(wa - __bfloat162float(ha)) : ha;
        __nv_bfloat16 vb = split ? __float2bfloat16(wb - __bfloat162float(hb)) : hb;
        g_wf[idx] = bfpack(va, vb);
    } else if (idx < 24576 + 1024) {
        int r2 = idx - 24576;
        int u = r2 & 3, lane = (r2 >> 2) & 31, kt = (r2 >> 7) & 3, tap = (r2 >> 9) & 1;
        int split = u >> 1, reg = u & 1;
        int n  = lane >> 2;
        int k0 = kt * 16 + (lane & 3) * 2 + reg * 8;
        float wa = cw4[(n * 64 + k0) * 2 + tap];
        float wb = cw4[(n * 64 + k0 + 1) * 2 + tap];
        __nv_bfloat16 ha = __float2bfloat16(wa), hb = __float2bfloat16(wb);
        __nv_bfloat16 va = split ? __float2bfloat16(wa - __bfloat162float(ha)) : ha;
        __nv_bfloat16 vb = split ? __float2bfloat16(wb - __bfloat162float(hb)) : hb;
        g_wf4[r2] = bfpack(va, vb);
    }
}

// -------- fused conv stack (HMMA) + softmax + MLP --------
__global__ __launch_bounds__(256)
void conv_mma_kernel(const float* __restrict__ x,
                     const float* __restrict__ cw0, const float* __restrict__ cb0,
                     const float* __restrict__ cb1, const float* __restrict__ cb2,
                     const float* __restrict__ cb3, const float* __restrict__ cb4,
                     const float* __restrict__ mw0, const float* __restrict__ mb0,
                     const float* __restrict__ mw1, const float* __restrict__ mb1,
                     const float* __restrict__ mw2, const float* __restrict__ mb2,
                     const float* __restrict__ gumbel,
                     float* __restrict__ out_z) {
    extern __shared__ char smem[];
    const uint32_t sb = smem_u32(smem);
    const int tid = threadIdx.x, wp = tid >> 5, lane = tid & 31;
    const int b = blockIdx.y;
    const int t0 = blockIdx.x * TS_OUT;
    const int mrow = wp * 16;

    float* xs   = (float*)(smem + XS_B);
    float* hs   = (float*)(smem + HS_B);
    float* cbs  = (float*)(smem + CBS_B);
    float* mw0s = (float*)(smem + MW0_B);
    float* mw1s = (float*)(smem + MW1_B);
    float* mw2s = (float*)(smem + MW2_B);
    float* mb0s = (float*)(smem + MB0_B);
    float* mb1s = (float*)(smem + MB1_B);
    float* mb2s = (float*)(smem + MB2_B);

    for (int j = tid; j < 132; j += 256) {
        int g = t0 + j - 31;
        xs[j] = (g >= 0 && g < T_LEN) ? __ldg(x + (size_t)b * T_LEN + g) : 0.f;
    }
    for (int i = tid; i < 200; i += 256)
        cbs[i] = (i < 64) ? __ldg(cb1 + i) : (i < 128) ? __ldg(cb2 + i - 64)
               : (i < 192) ? __ldg(cb3 + i - 128) : __ldg(cb4 + i - 192);
    mw0s[tid] = __ldg(mw0 + tid);
    mw1s[tid] = __ldg(mw1 + tid);
    if (tid < 16) { mw2s[tid] = mw2[tid]; mb0s[tid] = mb0[tid]; mb1s[tid] = mb1[tid]; }
    if (tid == 0) mb2s[0] = mb2[0];
    // zero halo rows 128..143 of both act arrays
    for (int i = tid; i < 576; i += 256) {
        int r = 128 + i / 36, w = i % 36;
        *(uint32_t*)(smem + ACTH_B + r * ACT_STRB + w * 4) = 0;
        *(uint32_t*)(smem + ACTL_B + r * ACT_STRB + w * 4) = 0;
    }
    __syncthreads();

    // ---- layer 0: 1 -> 64, d=1 (scalar, all 256 threads: 2 per row) ----
    {
        const int row = tid & 127, half = tid >> 7;
        float xa = xs[row], xb = xs[row + 1];
        char* ph = smem + ACTH_B + row * ACT_STRB + half * 64;
        char* pl = smem + ACTL_B + row * ACT_STRB + half * 64;
        const int cb_ = half * 32;
#pragma unroll 4
        for (int cc = 0; cc < 32; cc += 2) {
            int c = cb_ + cc;
            float v0 = rrelu(__ldg(cb0 + c)     + __ldg(cw0 + 2 * c)     * xa + __ldg(cw0 + 2 * c + 1) * xb);
            float v1 = rrelu(__ldg(cb0 + c + 1) + __ldg(cw0 + 2 * c + 2) * xa + __ldg(cw0 + 2 * c + 3) * xb);
            uint32_t hi, lo;
            split_pack(v0, v1, hi, lo);
            *(uint32_t*)(ph + 2 * cc) = hi;
            *(uint32_t*)(pl + 2 * cc) = lo;
        }
    }
    __syncthreads();

    // ---- mid layers via mma.sync (weights: inner-loop __ldg, L1-resident) ----
    const uint4* wfv = (const uint4*)g_wf;
    const int dil[3] = {2, 4, 8};
#pragma unroll
    for (int l = 0; l < 3; l++) {
        const int D = dil[l];
        float acc[8][4];
#pragma unroll
        for (int nt = 0; nt < 8; nt++)
#pragma unroll
            for (int q = 0; q < 4; q++) acc[nt][q] = 0.f;

#pragma unroll
        for (int tap = 0; tap < 2; tap++) {
            uint32_t abase = sb + (uint32_t)(mrow + tap * D + (lane & 15)) * ACT_STRB + (lane & 16);
#pragma unroll
            for (int kt = 0; kt < 4; kt++) {
                uint32_t ah[4], al[4];
                ldmx4(ah, abase + ACTH_B + kt * 32);
                ldmx4(al, abase + ACTL_B + kt * 32);
#pragma unroll
                for (int nt = 0; nt < 8; nt++) {
                    uint4 bv = __ldg(wfv + ((((l * 2 + tap) * 8 + nt) * 4 + kt) << 5) + lane);
                    mma16816(acc[nt], ah, bv.x, bv.y);
                    mma16816(acc[nt], al, bv.x, bv.y);
                    mma16816(acc[nt], ah, bv.z, bv.w);
                }
            }
        }
        __syncthreads();  // all reads of act done
        // epilogue: bias + rrelu + split, overwrite act rows 0..127
        const float* bias = cbs + 64 * l;
        const int r1 = mrow + (lane >> 2);
#pragma unroll
        for (int nt = 0; nt < 8; nt++) {
            int c0 = nt * 8 + (lane & 3) * 2;
            uint32_t hi, lo;
            split_pack(rrelu(acc[nt][0] + bias[c0]), rrelu(acc[nt][1] + bias[c0 + 1]), hi, lo);
            *(uint32_t*)(smem + ACTH_B + r1 * ACT_STRB + c0 * 2) = hi;
            *(uint32_t*)(smem + ACTL_B + r1 * ACT_STRB + c0 * 2) = lo;
            split_pack(rrelu(acc[nt][2] + bias[c0]), rrelu(acc[nt][3] + bias[c0 + 1]), hi, lo);
            *(uint32_t*)(smem + ACTH_B + (r1 + 8) * ACT_STRB + c0 * 2) = hi;
            *(uint32_t*)(smem + ACTL_B + (r1 + 8) * ACT_STRB + c0 * 2) = lo;
        }
        __syncthreads();
    }

    // ---- layer 4: 64 -> 8, d=16, N=8 (warps 0..5, rows 0..95) ----
    if (wp < 6) {
        float a4[4] = {0.f, 0.f, 0.f, 0.f};
#pragma unroll
        for (int tap = 0; tap < 2; tap++) {
            uint32_t abase = sb + (uint32_t)(mrow + tap * 16 + (lane & 15)) * ACT_STRB + (lane & 16);
#pragma unroll
            for (int kt = 0; kt < 4; kt++) {
                uint32_t ah[4], al[4];
                ldmx4(ah, abase + ACTH_B + kt * 32);
                ldmx4(al, abase + ACTL_B + kt * 32);
                uint4 bv = __ldg(((const uint4*)g_wf4) + (((tap * 4 + kt) << 5) + lane));
                mma16816(a4, ah, bv.x, bv.y);
                mma16816(a4, al, bv.x, bv.y);
                mma16816(a4, ah, bv.z, bv.w);
            }
        }
        const int r1 = mrow + (lane >> 2), c0 = (lane & 3) * 2;
        hs[r1 * 8 + c0]           = rrelu(a4[0] + cbs[192 + c0]);
        hs[r1 * 8 + c0 + 1]       = rrelu(a4[1] + cbs[192 + c0 + 1]);
        hs[(r1 + 8) * 8 + c0]     = rrelu(a4[2] + cbs[192 + c0]);
        hs[(r1 + 8) * 8 + c0 + 1] = rrelu(a4[3] + cbs[192 + c0 + 1]);
    }
    __syncthreads();

    // ---- gumbel softmax + MLP + mus ----
    {
        const int j = tid, t = t0 + j;
        if (j < TS_OUT && t < T_LEN) {
            float l8[8], gmb[8];
#pragma unroll
            for (int r = 0; r < 8; r++) l8[r] = hs[j * 8 + r];
            const float4* gp = (const float4*)(gumbel + ((size_t)b * T_LEN + t) * 8);
            float4 g0 = __ldg(gp), g1 = __ldg(gp + 1);
            gmb[0] = g0.x; gmb[1] = g0.y; gmb[2] = g0.z; gmb[3] = g0.w;
            gmb[4] = g1.x; gmb[5] = g1.y; gmb[6] = g1.z; gmb[7] = g1.w;
            float a[8], mx = -1e30f;
#pragma unroll
            for (int r = 0; r < 8; r++) { a[r] = (l8[r] + gmb[r]) * 10.f; mx = fmaxf(mx, a[r]); }
            float e[8], s = 0.f;
#pragma unroll
            for (int r = 0; r < 8; r++) { e[r] = __expf(a[r] - mx); s += e[r]; }
            float inv = 1.f / s;
            float z[8];
#pragma unroll
            for (int r = 0; r < 8; r++) {
                z[r] = e[r] * inv;
                out_z[((size_t)b * 8 + r) * T_LEN + t] = z[r];
            }
            float v[16];
#pragma unroll
            for (int r = 0; r < 8; r++) { v[r] = z[r]; v[8 + r] = l8[r]; }
            float m1[16];
#pragma unroll
            for (int o = 0; o < 16; o++) {
                float s2 = mb0s[o];
#pragma unroll
                for (int ci = 0; ci < 16; ci++) s2 += mw0s[o * 16 + ci] * v[ci];
                m1[o] = rrelu(s2);
            }
            float m2[16];
#pragma unroll
            for (int o = 0; o < 16; o++) {
                float s2 = mb1s[o];
#pragma unroll
                for (int ci = 0; ci < 16; ci++) s2 += mw1s[o * 16 + ci] * m1[ci];
                m2[o] = rrelu(s2);
            }
            float mu = mb2s[0];
#pragma unroll
            for (int ci = 0; ci < 16; ci++) mu += mw2s[ci] * m2[ci];
            g_mus[(size_t)b * T_LEN + t] = mu;
        }
    }
}

// -------- epilogue: windowed Fisher correction (proven) --------
__global__ __launch_bounds__(256)
void final_kernel(const float* __restrict__ x,
                  const float* __restrict__ sqrt_cov,
                  const float* __restrict__ fish,
                  const float* __restrict__ z_all,
                  float* __restrict__ out_mus) {
    __shared__ float xsm[288], msm[288], fsh[256], scs[8];
    const int tid = threadIdx.x;
    const int b   = blockIdx.y;
    const int p0  = blockIdx.x * 256;

    for (int i = tid; i < 288; i += 256) {
        int g = p0 + i;
        bool ok = g < T_LEN;
        xsm[i] = ok ? __ldg(x + (size_t)b * T_LEN + g) : 0.f;
        msm[i] = ok ? g_mus[(size_t)b * T_LEN + g] : 0.f;
    }
    if (tid < 256) fsh[tid] = __ldg(fish + tid);
    if (tid < 8)   scs[tid] = __ldg(sqrt_cov + tid);
    __syncthreads();

    const int p = p0 + tid;
    if (p < T_LEN - 32) {
        const int tau = p + 32;
        float z[8], cov = 0.f;
#pragma unroll
        for (int r = 0; r < 8; r++) {
            z[r] = __ldg(z_all + ((size_t)b * 8 + r) * T_LEN + tau);
            cov += z[r] * scs[r];
        }
        cov *= cov;
        float fj[32];
#pragma unroll
        for (int w = 0; w < 32; w++) fj[w] = 0.f;
#pragma unroll
        for (int r = 0; r < 8; r++)
#pragma unroll
            for (int w = 0; w < 32; w++)
                fj[w] += z[r] * fsh[r * 32 + w];
        float s = 0.f;
#pragma unroll
        for (int w = 0; w < 32; w++)
            s += fj[w] * (xsm[tid + w] - msm[tid + w]);
        out_mus[(size_t)b * (T_LEN - 32) + p] = msm[tid + 32] - cov * s;
    }
}

extern "C" void kernel_launch(void* const* d_in, const int* in_sizes, int n_in,
                              void* d_out, int out_size) {
    const float* x    = (const float*)d_in[0];
    const float* cw0  = (const float*)d_in[1];
    const float* cb0  = (const float*)d_in[2];
    const float* cw1  = (const float*)d_in[3];
    const float* cb1  = (const float*)d_in[4];
    const float* cw2  = (const float*)d_in[5];
    const float* cb2  = (const float*)d_in[6];
    const float* cw3  = (const float*)d_in[7];
    const float* cb3  = (const float*)d_in[8];
    const float* cw4  = (const float*)d_in[9];
    const float* cb4  = (const float*)d_in[10];
    const float* mw0  = (const float*)d_in[11];
    const float* mb0  = (const float*)d_in[12];
    const float* mw1  = (const float*)d_in[13];
    const float* mb1  = (const float*)d_in[14];
    const float* mw2  = (const float*)d_in[15];
    const float* mb2  = (const float*)d_in[16];
    const float* scv  = (const float*)d_in[17];
    const float* fish = (const float*)d_in[18];
    const float* gmb  = (const float*)d_in[19];

    float* out     = (float*)d_out;
    float* out_mus = out;
    float* out_z   = out + MUS_N;

    cudaFuncSetAttribute(conv_mma_kernel, cudaFuncAttributeMaxDynamicSharedMemorySize, SMEM_TOTAL);

    reorder_kernel<<<100, 256>>>(cw1, cw2, cw3, cw4);
    conv_mma_kernel<<<dim3(NBLK, B_SZ), 256, SMEM_TOTAL>>>(
        x, cw0, cb0, cb1, cb2, cb3, cb4, mw0, mb0, mw1, mb1, mw2, mb2, gmb, out_z);
    final_kernel<<<dim3((T_LEN - 32 + 255) / 256, B_SZ), 256>>>(x, scv, fish, out_z, out_mus);
}